// round 6
// baseline (speedup 1.0000x reference)
#include <cuda_runtime.h>

#define TSEQ  128
#define BATCH 4096

// Inter-layer sequence scratch (static device globals; no allocation anywhere).
// L3 output aliases the front of d_seq1 (seq1 is dead once L2 finished reading it).
__device__ float d_seq1[(size_t)BATCH * TSEQ * 128]; // L1 out [B,T,128]; front reused as L3 out [B,T,32]
__device__ float d_seq2[(size_t)BATCH * TSEQ * 64];  // L2 out [B,T,64]
__device__ float d_h4[BATCH * 8];                    // L4 final states [B,8]

__device__ __forceinline__ float fsig(float x) {
    return 1.0f / (1.0f + __expf(-x));
}
__device__ __forceinline__ float ftanh(float x) {
    float e = __expf(2.0f * x);
    return 1.0f - 2.0f / (e + 1.0f);
}

// ---- packed f32x2 helpers (Blackwell FFMA2: only reachable via PTX) ----
__device__ __forceinline__ void ffma2(unsigned long long& acc,
                                      unsigned long long a, unsigned long long b) {
    asm("fma.rn.f32x2 %0, %1, %2, %0;" : "+l"(acc) : "l"(a), "l"(b));
}
__device__ __forceinline__ unsigned long long pack2(float lo, float hi) {
    unsigned long long r;
    asm("mov.b64 %0, {%1, %2};" : "=l"(r) : "f"(lo), "f"(hi));
    return r;
}
__device__ __forceinline__ float2 unpack2(unsigned long long v) {
    float2 r;
    asm("mov.b64 {%0, %1}, %2;" : "=f"(r.x), "=f"(r.y) : "l"(v));
    return r;
}

// Buffer tags: 0 = kernel param, 1 = d_seq1, 2 = d_seq2, 3 = d_seq1 (as L3 out)
template<int TAG>
__device__ __forceinline__ float* buf_ptr(float* param) {
    if (TAG == 1 || TAG == 3) return d_seq1;
    if (TAG == 2) return d_seq2;
    return param;
}

// Fused bidirectional LSTM layer (layers 1-3).
//   grid = (BATCH/BT, 2)  [y: 0=forward, 1=backward]
//   Thread (tj, tb): 8 gate columns (2 hidden units x 4 gates) for BPT batch rows.
//   Weights permuted in smem to [k][jh*4+gate]; GEMM uses packed f32x2 FMA:
//   one LDS.128 of w = two packed (w0,w1) operands, v broadcast-duplicated once
//   per (k,row) with mov.b64.
template<int D, int H, int BT, int BPT, int SRC, int DST>
__global__ void __launch_bounds__((H / 2) * (BT / BPT))
lstm_layer(float* __restrict__ in_param, float* __restrict__ out_param,
           const float* __restrict__ WkF, const float* __restrict__ WrF, const float* __restrict__ bF,
           const float* __restrict__ WkB, const float* __restrict__ WrB, const float* __restrict__ bB)
{
    constexpr int NG = 4 * H;
    constexpr int TJ = NG / 8;       // threads along j (= H/2)
    constexpr int TB = BT / BPT;     // threads along batch
    constexpr int NT = TJ * TB;
    constexpr int DS = (D % 2 == 0) ? D + 1 : D;  // padded strides (bank conflicts)
    constexpr int HS = H + 1;

    const float* in = buf_ptr<SRC>(in_param);
    float* out = buf_ptr<DST>(out_param);

    extern __shared__ float sm[];
    float* sWk = sm;                 // [D][NG] permuted
    float* sWr = sWk + D * NG;       // [H][NG] permuted
    float* sB  = sWr + H * NG;       // [NG]    permuted
    float* sH  = sB + NG;            // [BT][HS]
    float* sX  = sH + BT * HS;       // [BT][DS]

    const int tid = threadIdx.x;
    const int tj  = tid % TJ;
    const int tb  = tid / TJ;
    const bool fwd = (blockIdx.y == 0);
    const float* Wk = fwd ? WkF : WkB;
    const float* Wr = fwd ? WrF : WrB;
    const float* bv = fwd ? bF  : bB;
    const int b0 = blockIdx.x * BT;

    // Load + permute weights: new col = jh*4+g  <-  old col = g*H+jh
    for (int i = tid; i < D * NG; i += NT) {
        int k = i / NG, col = i - k * NG;
        sWk[i] = Wk[k * NG + (col & 3) * H + (col >> 2)];
    }
    for (int i = tid; i < H * NG; i += NT) {
        int k = i / NG, col = i - k * NG;
        sWr[i] = Wr[k * NG + (col & 3) * H + (col >> 2)];
    }
    for (int i = tid; i < NG; i += NT)
        sB[i] = bv[(i & 3) * H + (i >> 2)];
    for (int i = tid; i < BT * HS; i += NT) sH[i] = 0.0f;
    __syncthreads();

    unsigned long long bj2[4];
#pragma unroll
    for (int q = 0; q < 4; q++) bj2[q] = pack2(sB[tj * 8 + 2 * q], sB[tj * 8 + 2 * q + 1]);

    float cst[BPT][2];
#pragma unroll
    for (int bi = 0; bi < BPT; bi++) { cst[bi][0] = 0.0f; cst[bi][1] = 0.0f; }

    const int jh0 = tj * 2;
    const float* wk = sWk + tj * 8;
    const float* wr = sWr + tj * 8;

    for (int s = 0; s < TSEQ; s++) {
        const int t = fwd ? s : (TSEQ - 1 - s);

        // stage x_t tile for this CTA's batch rows
        {
            const float* inb = in + ((size_t)b0 * TSEQ + t) * D;
            for (int i = tid; i < BT * D; i += NT) {
                int b = i / D, k = i - b * D;
                sX[b * DS + k] = inb[(size_t)b * TSEQ * D + k];
            }
        }
        __syncthreads();   // sX staged + previous-step sH writes visible

        unsigned long long acc2[BPT][4];
#pragma unroll
        for (int bi = 0; bi < BPT; bi++)
#pragma unroll
            for (int q = 0; q < 4; q++) acc2[bi][q] = bj2[q];

        // z += x_t @ Wk
#pragma unroll 2
        for (int k = 0; k < D; k++) {
            const ulonglong2* wp = (const ulonglong2*)(wk + k * NG);
            ulonglong2 wA = wp[0];   // packed cols (0,1),(2,3)
            ulonglong2 wB = wp[1];   // packed cols (4,5),(6,7)
#pragma unroll
            for (int bi = 0; bi < BPT; bi++) {
                float v = sX[(tb * BPT + bi) * DS + k];
                unsigned long long v2 = pack2(v, v);
                ffma2(acc2[bi][0], v2, wA.x);
                ffma2(acc2[bi][1], v2, wA.y);
                ffma2(acc2[bi][2], v2, wB.x);
                ffma2(acc2[bi][3], v2, wB.y);
            }
        }
        // z += h_{t-1} @ Wr
#pragma unroll 2
        for (int k = 0; k < H; k++) {
            const ulonglong2* wp = (const ulonglong2*)(wr + k * NG);
            ulonglong2 wA = wp[0];
            ulonglong2 wB = wp[1];
#pragma unroll
            for (int bi = 0; bi < BPT; bi++) {
                float v = sH[(tb * BPT + bi) * HS + k];
                unsigned long long v2 = pack2(v, v);
                ffma2(acc2[bi][0], v2, wA.x);
                ffma2(acc2[bi][1], v2, wA.y);
                ffma2(acc2[bi][2], v2, wB.x);
                ffma2(acc2[bi][3], v2, wB.y);
            }
        }
        __syncthreads();   // everyone done reading old sH / sX

        // gates: cols jh*4+g, pairs (i,f) and (g,o) per hidden unit
#pragma unroll
        for (int bi = 0; bi < BPT; bi++) {
            const int b = tb * BPT + bi;
            float h2[2];
#pragma unroll
            for (int jj = 0; jj < 2; jj++) {
                float2 pif = unpack2(acc2[bi][jj * 2 + 0]);  // (zi, zf)
                float2 pgo = unpack2(acc2[bi][jj * 2 + 1]);  // (zg, zo)
                float cc = fsig(pif.y) * cst[bi][jj] + fsig(pif.x) * ftanh(pgo.x);
                cst[bi][jj] = cc;
                h2[jj] = fsig(pgo.y) * ftanh(cc);
                sH[b * HS + jh0 + jj] = h2[jj];
            }
            float2 hv = make_float2(h2[0], h2[1]);
            *(float2*)(out + ((size_t)(b0 + b) * TSEQ + t) * (2 * H)
                           + (fwd ? 0 : H) + jh0) = hv;
        }
        __syncthreads();   // new sH published before next step's GEMM
    }
}

// Layer 4 (D=32, H=4, return final state only).
// 4 threads per (row, direction): thread handles ONE hidden unit (4 gate cols).
// h exchanged across the lane-quad with __shfl_sync; c scalar in register.
// x double-buffered in registers. No __syncthreads in the time loop.
// grid (BATCH/32, 2), 128 threads: tid = rl*4 + unit.
__global__ void __launch_bounds__(128)
lstm_l4(const float* __restrict__ WkF, const float* __restrict__ WrF, const float* __restrict__ bF,
        const float* __restrict__ WkB, const float* __restrict__ WrB, const float* __restrict__ bB)
{
    const float* in = d_seq1;        // L3 output, [B][T][32]
    const int tid  = threadIdx.x;
    const int unit = tid & 3;
    const int rl   = tid >> 2;       // 0..31
    const int lane = tid & 31;
    const bool fwd = (blockIdx.y == 0);
    const int row  = blockIdx.x * 32 + rl;

    __shared__ alignas(16) float sWk[32 * 16];   // permuted [k][j*4+g]
    __shared__ alignas(16) float sWr[4 * 16];
    __shared__ alignas(16) float sB[16];

    const float* Wk = fwd ? WkF : WkB;
    const float* Wr = fwd ? WrF : WrB;
    const float* bv = fwd ? bF  : bB;

    for (int i = tid; i < 32 * 16; i += 128) {
        int k = i >> 4, col = i & 15;
        sWk[i] = Wk[k * 16 + (col & 3) * 4 + (col >> 2)];
    }
    if (tid < 4 * 16) {
        int k = tid >> 4, col = tid & 15;
        sWr[tid] = Wr[k * 16 + (col & 3) * 4 + (col >> 2)];
    }
    if (tid < 16) sB[tid] = bv[(tid & 3) * 4 + (tid >> 2)];
    __syncthreads();

    float bz[4];
#pragma unroll
    for (int q = 0; q < 4; q++) bz[q] = sB[unit * 4 + q];

    float h = 0.0f, c = 0.0f;

    const float* base = in + (size_t)row * TSEQ * 32;
    float4 xa[8], xb[8];
    {
        const float4* p = (const float4*)(base + (fwd ? 0 : (TSEQ - 1)) * 32);
#pragma unroll
        for (int i = 0; i < 8; i++) xa[i] = p[i];
    }

#pragma unroll 1
    for (int s = 0; s < TSEQ; s++) {
        // prefetch x_{t+1}
        if (s + 1 < TSEQ) {
            const int tn = fwd ? (s + 1) : (TSEQ - 2 - s);
            const float4* p = (const float4*)(base + tn * 32);
#pragma unroll
            for (int i = 0; i < 8; i++) xb[i] = p[i];
        }

        float z[4];
#pragma unroll
        for (int q = 0; q < 4; q++) z[q] = bz[q];

        // z += x_t @ Wk  (this unit's 4 gate cols)
#pragma unroll
        for (int k = 0; k < 32; k++) {
            float v = ((const float*)xa)[k];
            float4 w = *(const float4*)(sWk + k * 16 + unit * 4);
            z[0] = fmaf(v, w.x, z[0]);
            z[1] = fmaf(v, w.y, z[1]);
            z[2] = fmaf(v, w.z, z[2]);
            z[3] = fmaf(v, w.w, z[3]);
        }
        // z += h_{t-1} @ Wr  (gather the quad's 4 h values via shuffle)
#pragma unroll
        for (int k = 0; k < 4; k++) {
            float hk = __shfl_sync(0xffffffffu, h, (lane & ~3) + k, 32);
            float4 w = *(const float4*)(sWr + k * 16 + unit * 4);
            z[0] = fmaf(hk, w.x, z[0]);
            z[1] = fmaf(hk, w.y, z[1]);
            z[2] = fmaf(hk, w.z, z[2]);
            z[3] = fmaf(hk, w.w, z[3]);
        }

        // gates for this unit: z = [i, f, g, o]
        float cc = fsig(z[1]) * c + fsig(z[0]) * ftanh(z[2]);
        c = cc;
        h = fsig(z[3]) * ftanh(cc);

#pragma unroll
        for (int i = 0; i < 8; i++) xa[i] = xb[i];
    }

    d_h4[(size_t)row * 8 + (fwd ? 0 : 4) + unit] = h;
}

__global__ void dense_sig(const float* __restrict__ W,
                          const float* __restrict__ bb, float* __restrict__ out)
{
    int b = blockIdx.x * blockDim.x + threadIdx.x;
    if (b >= BATCH) return;
    const float* hr = d_h4 + (size_t)b * 8;
    float hv[8];
#pragma unroll
    for (int j = 0; j < 8; j++) hv[j] = hr[j];
#pragma unroll
    for (int m = 0; m < 3; m++) {
        float a = bb[m];
#pragma unroll
        for (int j = 0; j < 8; j++) a = fmaf(hv[j], W[j * 3 + m], a);
        out[(size_t)b * 3 + m] = fsig(a);
    }
}

static size_t smem_bytes(int D, int H, int BT) {
    int NG = 4 * H;
    int DS = (D % 2 == 0) ? D + 1 : D;
    int HS = H + 1;
    return (size_t)(D * NG + H * NG + NG + BT * HS + BT * DS) * sizeof(float);
}

extern "C" void kernel_launch(void* const* d_in, const int* in_sizes, int n_in,
                              void* d_out, int out_size)
{
    (void)in_sizes; (void)n_in; (void)out_size;
    float* x = (float*)d_in[0];
    const float* p[24];
    for (int i = 0; i < 24; i++) p[i] = (const float*)d_in[1 + i];
    const float* dW = (const float*)d_in[25];
    const float* db = (const float*)d_in[26];

    size_t s1 = smem_bytes(78, 64, 64);
    size_t s2 = smem_bytes(128, 32, 64);
    size_t s3 = smem_bytes(64, 16, 64);
    cudaFuncSetAttribute(lstm_layer<78, 64, 64, 8, 0, 1>,
                         cudaFuncAttributeMaxDynamicSharedMemorySize, (int)s1);
    cudaFuncSetAttribute(lstm_layer<128, 32, 64, 4, 1, 2>,
                         cudaFuncAttributeMaxDynamicSharedMemorySize, (int)s2);
    cudaFuncSetAttribute(lstm_layer<64, 16, 64, 2, 2, 3>,
                         cudaFuncAttributeMaxDynamicSharedMemorySize, (int)s3);

    // L1: x -> seq1 (78 -> 2*64), grid (64,2), 256 thr
    lstm_layer<78, 64, 64, 8, 0, 1><<<dim3(BATCH / 64, 2), 256, s1>>>(
        x, nullptr, p[0], p[1], p[2], p[3], p[4], p[5]);
    // L2: seq1 -> seq2 (128 -> 2*32)
    lstm_layer<128, 32, 64, 4, 1, 2><<<dim3(BATCH / 64, 2), 256, s2>>>(
        nullptr, nullptr, p[6], p[7], p[8], p[9], p[10], p[11]);
    // L3: seq2 -> seq3(=seq1 front) (64 -> 2*16)
    lstm_layer<64, 16, 64, 2, 2, 3><<<dim3(BATCH / 64, 2), 256, s3>>>(
        nullptr, nullptr, p[12], p[13], p[14], p[15], p[16], p[17]);
    // L4: seq3 -> h4 final states [B,8], 4 threads/row, shuffle-coupled
    lstm_l4<<<dim3(BATCH / 32, 2), 128>>>(p[18], p[19], p[20], p[21], p[22], p[23]);
    // dense 8->3 + sigmoid
    dense_sig<<<(BATCH + 255) / 256, 256>>>(dW, db, (float*)d_out);
}